// round 1
// baseline (speedup 1.0000x reference)
#include <cuda_runtime.h>
#include <math.h>

// Problem constants
#define B_SZ 4
#define NSEQ 2048
#define CDIM 1024
#define NHEAD 16
#define HD 64
#define MROWS (B_SZ * NSEQ)        // 8192
#define QKVDIM (3 * CDIM)          // 3072
#define BHTOT (B_SZ * NHEAD)       // 64

// Scratch (static device allocations — allocation-free kernel_launch)
__device__ float g_qkv[MROWS * QKVDIM];          // [8192][3072]
__device__ float g_q[BHTOT * NSEQ * HD];         // [64][2048][64]
__device__ float g_k[BHTOT * NSEQ * HD];
__device__ float g_v[BHTOT * NSEQ * HD];
__device__ float g_att[MROWS * CDIM];            // [8192][1024]

// ---------------------------------------------------------------------------
// SGEMM (NT): C[m,n] = sum_k A[m,k] * B[n,k] (+ bias[n])
// 128x128 block tile, BK=16, 8x8 per-thread tile, 256 threads.
// Assumes M%128==0, N%128==0, K%16==0 (true for all our shapes).
// ---------------------------------------------------------------------------
template <bool BIAS>
__global__ __launch_bounds__(256) void sgemm_nt(
    const float* __restrict__ A, const float* __restrict__ B,
    const float* __restrict__ bias, float* __restrict__ C,
    int M, int N, int K)
{
    __shared__ float As[16][132];
    __shared__ float Bs[16][132];

    const int tid = threadIdx.x;
    const int m0 = blockIdx.y * 128;
    const int n0 = blockIdx.x * 128;
    const int tx = tid & 15;
    const int ty = tid >> 4;

    float acc[8][8];
#pragma unroll
    for (int i = 0; i < 8; i++)
#pragma unroll
        for (int j = 0; j < 8; j++) acc[i][j] = 0.f;

    for (int kt = 0; kt < K; kt += 16) {
#pragma unroll
        for (int i = 0; i < 2; i++) {
            int f = tid + i * 256;          // 0..511
            int row = f >> 2;               // 0..127
            int kc = (f & 3) << 2;          // 0,4,8,12
            float4 av = *reinterpret_cast<const float4*>(
                &A[(size_t)(m0 + row) * K + kt + kc]);
            As[kc + 0][row] = av.x; As[kc + 1][row] = av.y;
            As[kc + 2][row] = av.z; As[kc + 3][row] = av.w;
            float4 bv = *reinterpret_cast<const float4*>(
                &B[(size_t)(n0 + row) * K + kt + kc]);
            Bs[kc + 0][row] = bv.x; Bs[kc + 1][row] = bv.y;
            Bs[kc + 2][row] = bv.z; Bs[kc + 3][row] = bv.w;
        }
        __syncthreads();
#pragma unroll
        for (int k = 0; k < 16; k++) {
            float a[8], b[8];
            float4 a0 = *reinterpret_cast<const float4*>(&As[k][ty * 8]);
            float4 a1 = *reinterpret_cast<const float4*>(&As[k][ty * 8 + 4]);
            a[0] = a0.x; a[1] = a0.y; a[2] = a0.z; a[3] = a0.w;
            a[4] = a1.x; a[5] = a1.y; a[6] = a1.z; a[7] = a1.w;
            float4 b0 = *reinterpret_cast<const float4*>(&Bs[k][tx * 8]);
            float4 b1 = *reinterpret_cast<const float4*>(&Bs[k][tx * 8 + 4]);
            b[0] = b0.x; b[1] = b0.y; b[2] = b0.z; b[3] = b0.w;
            b[4] = b1.x; b[5] = b1.y; b[6] = b1.z; b[7] = b1.w;
#pragma unroll
            for (int i = 0; i < 8; i++)
#pragma unroll
                for (int j = 0; j < 8; j++)
                    acc[i][j] = fmaf(a[i], b[j], acc[i][j]);
        }
        __syncthreads();
    }

    float bv[8];
#pragma unroll
    for (int j = 0; j < 8; j++) bv[j] = BIAS ? bias[n0 + tx * 8 + j] : 0.f;

#pragma unroll
    for (int i = 0; i < 8; i++) {
        size_t m = (size_t)(m0 + ty * 8 + i);
        float4 c0, c1;
        c0.x = acc[i][0] + bv[0]; c0.y = acc[i][1] + bv[1];
        c0.z = acc[i][2] + bv[2]; c0.w = acc[i][3] + bv[3];
        c1.x = acc[i][4] + bv[4]; c1.y = acc[i][5] + bv[5];
        c1.z = acc[i][6] + bv[6]; c1.w = acc[i][7] + bv[7];
        *reinterpret_cast<float4*>(&C[m * N + n0 + tx * 8]) = c0;
        *reinterpret_cast<float4*>(&C[m * N + n0 + tx * 8 + 4]) = c1;
    }
}

// ---------------------------------------------------------------------------
// Prep: split qkv, RMSNorm(q,k), RoPE(q,k), write Q/K/V as [b*H+h][n][64]
// One block (64 threads) per (b,n,h).
// ---------------------------------------------------------------------------
__global__ __launch_bounds__(64) void prep_kernel(
    const float* __restrict__ qkv,
    const float* __restrict__ cosb, const float* __restrict__ sinb,
    const float* __restrict__ qw, const float* __restrict__ kw,
    float* __restrict__ Q, float* __restrict__ K, float* __restrict__ V)
{
    const int bn = blockIdx.x;           // b*2048 + n
    const int h = blockIdx.y;
    const int t = threadIdx.x;           // 0..63
    const int b = bn >> 11;
    const int n = bn & 2047;

    const float* base = qkv + (size_t)bn * QKVDIM;
    float q = base[h * HD + t];
    float k = base[CDIM + h * HD + t];
    float v = base[2 * CDIM + h * HD + t];

    __shared__ float red[128];
    __shared__ float sq[64];
    __shared__ float sk[64];

    red[t] = q * q;
    red[64 + t] = k * k;
    __syncthreads();
#pragma unroll
    for (int s = 32; s > 0; s >>= 1) {
        if (t < s) { red[t] += red[t + s]; red[64 + t] += red[64 + t + s]; }
        __syncthreads();
    }
    float qn = q * rsqrtf(red[0] * (1.f / 64.f) + 1e-6f) * qw[t];
    float kn = k * rsqrtf(red[64] * (1.f / 64.f) + 1e-6f) * kw[t];
    sq[t] = qn;
    sk[t] = kn;
    __syncthreads();
    float qr = (t < 32) ? -sq[t + 32] : sq[t - 32];
    float kr = (t < 32) ? -sk[t + 32] : sk[t - 32];
    float cv = cosb[n * HD + t];
    float sv = sinb[n * HD + t];

    size_t idx = (((size_t)(b * NHEAD + h)) * NSEQ + n) * HD + t;
    Q[idx] = qn * cv + qr * sv;
    K[idx] = kn * cv + kr * sv;
    V[idx] = v;
}

// ---------------------------------------------------------------------------
// Flash attention: one block per (b*H+h, q-tile of 64). 256 threads.
// Shared layouts (stride PAD=68, keeps float4 alignment):
//   QsT[k][r]  (transposed)   KVs: K as [k][c] (transposed), V as [c][d]
//   SsT[c][r]  (transposed)   => all hot LDS are conflict-free float4
// ---------------------------------------------------------------------------
#define PAD 68
#define FA_SMEM (3 * 64 * PAD * 4)

__global__ __launch_bounds__(256) void flash_attn(
    const float* __restrict__ Qg, const float* __restrict__ Kg,
    const float* __restrict__ Vg, float* __restrict__ O)
{
    extern __shared__ float sm[];
    float* QsT = sm;                 // 64*PAD
    float* KVs = sm + 64 * PAD;      // 64*PAD
    float* SsT = sm + 2 * 64 * PAD;  // 64*PAD

    const int bh = blockIdx.x;       // 0..63
    const int qt = blockIdx.y;       // 0..31
    const int b = bh >> 4, h = bh & 15;
    const int t = threadIdx.x;
    const int tx = t & 15;           // column group (cols tx*4..+3)
    const int ty = t >> 4;           // row group   (rows ty*4..+3)

    const float* Qb = Qg + ((size_t)bh * NSEQ + qt * 64) * HD;
    const float* Kb = Kg + (size_t)bh * NSEQ * HD;
    const float* Vb = Vg + (size_t)bh * NSEQ * HD;

    // load Q tile (transposed into QsT[k][r])
#pragma unroll
    for (int i = 0; i < 4; i++) {
        int f = t + i * 256;
        int row = f >> 4;
        int c4 = (f & 15) << 2;
        float4 qv = *reinterpret_cast<const float4*>(&Qb[row * HD + c4]);
        QsT[(c4 + 0) * PAD + row] = qv.x;
        QsT[(c4 + 1) * PAD + row] = qv.y;
        QsT[(c4 + 2) * PAD + row] = qv.z;
        QsT[(c4 + 3) * PAD + row] = qv.w;
    }

    float m[4], l[4];
    float4 o4[4];
#pragma unroll
    for (int i = 0; i < 4; i++) {
        m[i] = -1e30f; l[i] = 0.f;
        o4[i] = make_float4(0.f, 0.f, 0.f, 0.f);
    }

    for (int j = 0; j < NSEQ / 64; j++) {
        __syncthreads();   // prev iter done with KVs/SsT
        // K tile -> KVs transposed [k][c]
#pragma unroll
        for (int i = 0; i < 4; i++) {
            int f = t + i * 256;
            int row = f >> 4;
            int c4 = (f & 15) << 2;
            float4 kv = *reinterpret_cast<const float4*>(
                &Kb[(size_t)(j * 64 + row) * HD + c4]);
            KVs[(c4 + 0) * PAD + row] = kv.x;
            KVs[(c4 + 1) * PAD + row] = kv.y;
            KVs[(c4 + 2) * PAD + row] = kv.z;
            KVs[(c4 + 3) * PAD + row] = kv.w;
        }
        __syncthreads();

        // S = Q K^T (4x4 per thread)
        float s[4][4];
#pragma unroll
        for (int i = 0; i < 4; i++)
#pragma unroll
            for (int jj = 0; jj < 4; jj++) s[i][jj] = 0.f;

#pragma unroll 4
        for (int k = 0; k < HD; k++) {
            float4 qq = *reinterpret_cast<const float4*>(&QsT[k * PAD + ty * 4]);
            float4 kk = *reinterpret_cast<const float4*>(&KVs[k * PAD + tx * 4]);
            float qa[4] = {qq.x, qq.y, qq.z, qq.w};
            float ka[4] = {kk.x, kk.y, kk.z, kk.w};
#pragma unroll
            for (int i = 0; i < 4; i++)
#pragma unroll
                for (int jj = 0; jj < 4; jj++)
                    s[i][jj] = fmaf(qa[i], ka[jj], s[i][jj]);
        }
#pragma unroll
        for (int i = 0; i < 4; i++)
#pragma unroll
            for (int jj = 0; jj < 4; jj++) s[i][jj] *= 0.125f;  // hd^-0.5

        // online softmax
        float mt[4];
#pragma unroll
        for (int i = 0; i < 4; i++)
            mt[i] = fmaxf(fmaxf(s[i][0], s[i][1]), fmaxf(s[i][2], s[i][3]));
#pragma unroll
        for (int off = 1; off < 16; off <<= 1) {
#pragma unroll
            for (int i = 0; i < 4; i++)
                mt[i] = fmaxf(mt[i], __shfl_xor_sync(0xffffffffu, mt[i], off));
        }
        float mn[4], fs[4], ps[4];
#pragma unroll
        for (int i = 0; i < 4; i++) {
            mn[i] = fmaxf(m[i], mt[i]);
            fs[i] = __expf(m[i] - mn[i]);
            m[i] = mn[i];
            ps[i] = 0.f;
        }
#pragma unroll
        for (int jj = 0; jj < 4; jj++) {
            float4 p;
            p.x = __expf(s[0][jj] - mn[0]);
            p.y = __expf(s[1][jj] - mn[1]);
            p.z = __expf(s[2][jj] - mn[2]);
            p.w = __expf(s[3][jj] - mn[3]);
            ps[0] += p.x; ps[1] += p.y; ps[2] += p.z; ps[3] += p.w;
            *reinterpret_cast<float4*>(&SsT[(tx * 4 + jj) * PAD + ty * 4]) = p;
        }
#pragma unroll
        for (int off = 1; off < 16; off <<= 1) {
#pragma unroll
            for (int i = 0; i < 4; i++)
                ps[i] += __shfl_xor_sync(0xffffffffu, ps[i], off);
        }
#pragma unroll
        for (int i = 0; i < 4; i++) {
            l[i] = l[i] * fs[i] + ps[i];
            o4[i].x *= fs[i]; o4[i].y *= fs[i];
            o4[i].z *= fs[i]; o4[i].w *= fs[i];
        }

        __syncthreads();   // done reading K from KVs, SsT fully written
        // V tile -> KVs natural [c][d]
#pragma unroll
        for (int i = 0; i < 4; i++) {
            int f = t + i * 256;
            int row = f >> 4;
            int c4 = (f & 15) << 2;
            *reinterpret_cast<float4*>(&KVs[row * PAD + c4]) =
                *reinterpret_cast<const float4*>(
                    &Vb[(size_t)(j * 64 + row) * HD + c4]);
        }
        __syncthreads();

        // O += P V
#pragma unroll 4
        for (int c = 0; c < 64; c++) {
            float4 pv = *reinterpret_cast<const float4*>(&SsT[c * PAD + ty * 4]);
            float4 vv = *reinterpret_cast<const float4*>(&KVs[c * PAD + tx * 4]);
            o4[0].x = fmaf(pv.x, vv.x, o4[0].x);
            o4[0].y = fmaf(pv.x, vv.y, o4[0].y);
            o4[0].z = fmaf(pv.x, vv.z, o4[0].z);
            o4[0].w = fmaf(pv.x, vv.w, o4[0].w);
            o4[1].x = fmaf(pv.y, vv.x, o4[1].x);
            o4[1].y = fmaf(pv.y, vv.y, o4[1].y);
            o4[1].z = fmaf(pv.y, vv.z, o4[1].z);
            o4[1].w = fmaf(pv.y, vv.w, o4[1].w);
            o4[2].x = fmaf(pv.z, vv.x, o4[2].x);
            o4[2].y = fmaf(pv.z, vv.y, o4[2].y);
            o4[2].z = fmaf(pv.z, vv.z, o4[2].z);
            o4[2].w = fmaf(pv.z, vv.w, o4[2].w);
            o4[3].x = fmaf(pv.w, vv.x, o4[3].x);
            o4[3].y = fmaf(pv.w, vv.y, o4[3].y);
            o4[3].z = fmaf(pv.w, vv.z, o4[3].z);
            o4[3].w = fmaf(pv.w, vv.w, o4[3].w);
        }
    }

    // epilogue: normalize and write [B,N,C] layout for proj GEMM
#pragma unroll
    for (int i = 0; i < 4; i++) {
        float inv = 1.0f / l[i];
        float4 v = o4[i];
        v.x *= inv; v.y *= inv; v.z *= inv; v.w *= inv;
        int row = qt * 64 + ty * 4 + i;
        *reinterpret_cast<float4*>(
            &O[((size_t)b * NSEQ + row) * CDIM + h * HD + tx * 4]) = v;
    }
}

// ---------------------------------------------------------------------------
extern "C" void kernel_launch(void* const* d_in, const int* in_sizes, int n_in,
                              void* d_out, int out_size)
{
    const float* x      = (const float*)d_in[0];
    const float* cosb   = (const float*)d_in[1];
    const float* sinb   = (const float*)d_in[2];
    const float* w_qkv  = (const float*)d_in[3];
    const float* w_proj = (const float*)d_in[4];
    const float* b_proj = (const float*)d_in[5];
    const float* qw     = (const float*)d_in[6];
    const float* kw     = (const float*)d_in[7];
    float* out = (float*)d_out;

    float *qkv, *Qp, *Kp, *Vp, *att;
    cudaGetSymbolAddress((void**)&qkv, g_qkv);
    cudaGetSymbolAddress((void**)&Qp, g_q);
    cudaGetSymbolAddress((void**)&Kp, g_k);
    cudaGetSymbolAddress((void**)&Vp, g_v);
    cudaGetSymbolAddress((void**)&att, g_att);

    // 1) qkv = x @ w_qkv^T
    sgemm_nt<false><<<dim3(QKVDIM / 128, MROWS / 128), 256>>>(
        x, w_qkv, nullptr, qkv, MROWS, QKVDIM, CDIM);

    // 2) split + rmsnorm + rope
    prep_kernel<<<dim3(MROWS, NHEAD), 64>>>(qkv, cosb, sinb, qw, kw, Qp, Kp, Vp);

    // 3) attention
    cudaFuncSetAttribute(flash_attn, cudaFuncAttributeMaxDynamicSharedMemorySize,
                         FA_SMEM);
    flash_attn<<<dim3(BHTOT, NSEQ / 64), 256, FA_SMEM>>>(Qp, Kp, Vp, att);

    // 4) out = att @ w_proj^T + b
    sgemm_nt<true><<<dim3(CDIM / 128, MROWS / 128), 256>>>(
        att, w_proj, b_proj, out, MROWS, CDIM, CDIM);
}